// round 1
// baseline (speedup 1.0000x reference)
#include <cuda_runtime.h>
#include <cstdint>

#define D      128
#define HH     8
#define DHH    16
#define RR     6
#define BB     6
#define MAXN   50000
#define KDIM   (RR * D)    /* 768 */
#define NOUT   (3 * D)     /* 384 */

// ---------------- scratch (static device globals; no allocation) ----------------
__device__ float g_S[(size_t)MAXN * KDIM];     // [N][R*D]  per-(dst,rel) feature sums
__device__ float g_W[KDIM * NOUT];             // [768][384] stacked relation weights (Q|K|V)
__device__ float g_bias[NOUT];                 // [384]
__device__ float g_QKV[(size_t)MAXN * NOUT];   // [N][384]  Q|K|V after relu(agg + bias)
__device__ float g_wV[(size_t)MAXN * D];       // [N][128]  attention numerator
__device__ float g_z[(size_t)MAXN * HH];       // [N][8]    attention denominator

// ---------------- zero scratch accumulators ----------------
__global__ void zero_all(int n) {
    size_t i = (size_t)blockIdx.x * blockDim.x + threadIdx.x;
    size_t stride = (size_t)gridDim.x * blockDim.x;
    float4 z = make_float4(0.f, 0.f, 0.f, 0.f);
    size_t nS = (size_t)n * KDIM / 4;
    for (size_t j = i; j < nS; j += stride) ((float4*)g_S)[j] = z;
    size_t nW = (size_t)n * D / 4;
    for (size_t j = i; j < nW; j += stride) ((float4*)g_wV)[j] = z;
    size_t nZ = (size_t)n * HH / 4;
    for (size_t j = i; j < nZ; j += stride) ((float4*)g_z)[j] = z;
}

// ---------------- build stacked W[k=r*128+i][o] = sum_b coef[r,b]*basis[b,i,o] ----------------
__global__ void build_W(const float* __restrict__ qb, const float* __restrict__ qc, const float* __restrict__ bq,
                        const float* __restrict__ kb, const float* __restrict__ kc, const float* __restrict__ bk,
                        const float* __restrict__ vb, const float* __restrict__ vc, const float* __restrict__ bv) {
    int idx = blockIdx.x * blockDim.x + threadIdx.x;
    if (idx < NOUT) {
        g_bias[idx] = (idx < D) ? bq[idx] : (idx < 2 * D) ? bk[idx - D] : bv[idx - 2 * D];
    }
    if (idx >= KDIM * NOUT) return;
    int k = idx / NOUT;
    int o = idx - k * NOUT;
    int r = k / D, i2 = k - r * D;
    const float* basis; const float* coef; int oo = o;
    if (o < D)          { basis = qb; coef = qc; }
    else if (o < 2 * D) { basis = kb; coef = kc; oo = o - D; }
    else                { basis = vb; coef = vc; oo = o - 2 * D; }
    float acc = 0.f;
#pragma unroll
    for (int b = 0; b < BB; b++)
        acc += coef[r * BB + b] * basis[(size_t)b * D * D + (size_t)i2 * D + oo];
    g_W[(size_t)k * NOUT + o] = acc;
}

// ---------------- scatter: S[dst, etype, :] += h[src, :]  (warp per edge, v4 float REDs) ----------------
__global__ void scatter_S(const float* __restrict__ h, const int* __restrict__ src,
                          const int* __restrict__ dst, const int* __restrict__ et, int E) {
    int warp = (blockIdx.x * blockDim.x + threadIdx.x) >> 5;
    if (warp >= E) return;
    int lane = threadIdx.x & 31;
    int s = __ldg(src + warp);
    int d0 = __ldg(dst + warp);
    int r = __ldg(et + warp);
    float4 v = __ldg((const float4*)(h + (size_t)s * D) + lane);
    float* p = g_S + ((size_t)d0 * KDIM + r * D + lane * 4);
    asm volatile("red.global.add.v4.f32 [%0], {%1,%2,%3,%4};"
                 :: "l"(p), "f"(v.x), "f"(v.y), "f"(v.z), "f"(v.w) : "memory");
}

// ---------------- SGEMM: QKV[M,384] = relu(S[M,768] @ W[768,384] + bias), packed f32x2 FMAs ----------------
__global__ __launch_bounds__(256, 1) void gemm_qkv(int M) {
    __shared__ __align__(16) float As[16][132];   // A tile transposed [k][m], +4 pad
    __shared__ __align__(16) float Bs[16][128];   // B tile [k][n]
    int t = threadIdx.x;
    int bn = blockIdx.x * 128;
    int bm = blockIdx.y * 128;
    int tx = t & 15, ty = t >> 4;

    unsigned long long acc[8][4];
#pragma unroll
    for (int i = 0; i < 8; i++)
#pragma unroll
        for (int j = 0; j < 4; j++) acc[i][j] = 0ULL;

    for (int k0 = 0; k0 < KDIM; k0 += 16) {
        // load A tile: 128 rows x 16 k  (512 float4, 2 per thread), transpose into As
#pragma unroll
        for (int ldi = 0; ldi < 2; ldi++) {
            int q = t + ldi * 256;
            int row = q >> 2;
            int kc = q & 3;
            int grow = bm + row;
            float4 a4 = make_float4(0.f, 0.f, 0.f, 0.f);
            if (grow < M) a4 = *(const float4*)(g_S + (size_t)grow * KDIM + k0 + kc * 4);
            As[kc * 4 + 0][row] = a4.x;
            As[kc * 4 + 1][row] = a4.y;
            As[kc * 4 + 2][row] = a4.z;
            As[kc * 4 + 3][row] = a4.w;
        }
        // load B tile: 16 k x 128 cols (512 float4, 2 per thread)
#pragma unroll
        for (int ldi = 0; ldi < 2; ldi++) {
            int q = t + ldi * 256;
            int krow = q >> 5;
            int col = (q & 31) * 4;
            *(float4*)(&Bs[krow][col]) = *(const float4*)(g_W + (size_t)(k0 + krow) * NOUT + bn + col);
        }
        __syncthreads();
#pragma unroll
        for (int kk = 0; kk < 16; kk++) {
            float4 a0 = *(const float4*)(&As[kk][ty * 8]);
            float4 a1 = *(const float4*)(&As[kk][ty * 8 + 4]);
            unsigned long long bp[4];
            const unsigned long long* bsl = (const unsigned long long*)(&Bs[kk][tx * 8]);
            bp[0] = bsl[0]; bp[1] = bsl[1]; bp[2] = bsl[2]; bp[3] = bsl[3];
            float av[8] = {a0.x, a0.y, a0.z, a0.w, a1.x, a1.y, a1.z, a1.w};
#pragma unroll
            for (int i = 0; i < 8; i++) {
                unsigned long long ap;
                asm("mov.b64 %0, {%1, %1};" : "=l"(ap) : "f"(av[i]));
#pragma unroll
                for (int j = 0; j < 4; j++)
                    asm("fma.rn.f32x2 %0, %1, %2, %0;" : "+l"(acc[i][j]) : "l"(ap), "l"(bp[j]));
            }
        }
        __syncthreads();
    }
    // epilogue: bias + relu
#pragma unroll
    for (int i = 0; i < 8; i++) {
        int grow = bm + ty * 8 + i;
        if (grow < M) {
#pragma unroll
            for (int j = 0; j < 4; j++) {
                float lo, hi;
                asm("mov.b64 {%0, %1}, %2;" : "=f"(lo), "=f"(hi) : "l"(acc[i][j]));
                int col = bn + tx * 8 + j * 2;
                float2 b2 = *(const float2*)(&g_bias[col]);
                lo = fmaxf(lo + b2.x, 0.f);
                hi = fmaxf(hi + b2.y, 0.f);
                *(float2*)(g_QKV + (size_t)grow * NOUT + col) = make_float2(lo, hi);
            }
        }
    }
}

// ---------------- attention: warp per edge ----------------
__global__ void attn_kernel(const int* __restrict__ src, const int* __restrict__ dst, int E) {
    int warp = (blockIdx.x * blockDim.x + threadIdx.x) >> 5;
    if (warp >= E) return;
    int lane = threadIdx.x & 31;
    int s = __ldg(src + warp);
    int d0 = __ldg(dst + warp);
    const float4* q4 = (const float4*)(g_QKV + (size_t)d0 * NOUT);
    const float4* k4 = (const float4*)(g_QKV + (size_t)s * NOUT + D);
    const float4* v4 = (const float4*)(g_QKV + (size_t)s * NOUT + 2 * D);
    float4 q = q4[lane], k = k4[lane], v = v4[lane];
    // lane owns cols lane*4..lane*4+3; head = lane/4; reduce dot across the 4 lanes of a head
    float p = q.x * k.x + q.y * k.y + q.z * k.z + q.w * k.w;
    p += __shfl_xor_sync(0xffffffffu, p, 1);
    p += __shfl_xor_sync(0xffffffffu, p, 2);
    float sc = fminf(fmaxf(p * 0.25f, -10.0f), 10.0f);   // SCALE = sqrt(16) = 4
    float w = expf(sc);
    float* pw = g_wV + ((size_t)d0 * D + lane * 4);
    asm volatile("red.global.add.v4.f32 [%0], {%1,%2,%3,%4};"
                 :: "l"(pw), "f"(v.x * w), "f"(v.y * w), "f"(v.z * w), "f"(v.w * w) : "memory");
    if ((lane & 3) == 0)
        atomicAdd(g_z + (size_t)d0 * HH + (lane >> 2), w);
}

// ---------------- finalize: out = wV / (z + 1e-6) ----------------
__global__ void finalize(float* __restrict__ out, int N) {
    int idx = blockIdx.x * blockDim.x + threadIdx.x;
    if (idx >= N * D) return;
    int n = idx >> 7;
    int c = idx & 127;
    out[idx] = g_wV[idx] / (g_z[n * HH + (c >> 4)] + 1e-6f);
}

extern "C" void kernel_launch(void* const* d_in, const int* in_sizes, int n_in,
                              void* d_out, int out_size) {
    const float* h   = (const float*)d_in[0];
    const int*   src = (const int*)d_in[1];
    const int*   dst = (const int*)d_in[2];
    const int*   et  = (const int*)d_in[3];
    const float* Wq_basis = (const float*)d_in[4];
    const float* Wq_coef  = (const float*)d_in[5];
    const float* bq       = (const float*)d_in[6];
    const float* Wk_basis = (const float*)d_in[7];
    const float* Wk_coef  = (const float*)d_in[8];
    const float* bk       = (const float*)d_in[9];
    const float* Wv_basis = (const float*)d_in[10];
    const float* Wv_coef  = (const float*)d_in[11];
    const float* bv       = (const float*)d_in[12];
    float* out = (float*)d_out;

    int N = in_sizes[0] / D;   // 50000
    int E = in_sizes[1];       // 500000

    zero_all<<<2048, 256>>>(N);
    build_W<<<(KDIM * NOUT + 255) / 256, 256>>>(Wq_basis, Wq_coef, bq,
                                                Wk_basis, Wk_coef, bk,
                                                Wv_basis, Wv_coef, bv);
    {
        long long threads = (long long)E * 32;
        int blocks = (int)((threads + 255) / 256);
        scatter_S<<<blocks, 256>>>(h, src, dst, et, E);
    }
    {
        dim3 gg(NOUT / 128, (N + 127) / 128);
        gemm_qkv<<<gg, 256>>>(N);
    }
    {
        long long threads = (long long)E * 32;
        int blocks = (int)((threads + 255) / 256);
        attn_kernel<<<blocks, 256>>>(src, dst, E);
    }
    finalize<<<(N * D + 255) / 256, 256>>>(out, N);
}

// round 3
// speedup vs baseline: 1.7620x; 1.7620x over previous
#include <cuda_runtime.h>
#include <cuda_bf16.h>
#include <cstdint>

#define D      128
#define HH     8
#define RR     6
#define BB     6
#define MAXN   50000
#define NPAD   50048              /* 391 * 128 */
#define KDIM   (RR * D)           /* 768 */
#define NOUT   (3 * D)            /* 384 */

// ---------------- scratch (static device globals; no allocation) ----------------
__device__ __align__(256) float g_S[(size_t)NPAD * KDIM];            // fp32 per-(dst,rel) sums
__device__ __align__(256) __nv_bfloat16 g_Shi[(size_t)NPAD * KDIM];
__device__ __align__(256) __nv_bfloat16 g_Slo[(size_t)NPAD * KDIM];
__device__ __align__(256) __nv_bfloat16 g_Wthi[(size_t)NOUT * KDIM]; // [384][768] K-major (W^T)
__device__ __align__(256) __nv_bfloat16 g_Wtlo[(size_t)NOUT * KDIM];
__device__ __align__(256) float g_bias[NOUT];
__device__ __align__(256) float g_QKV[(size_t)NPAD * NOUT];          // relu(S@W + b)
__device__ __align__(256) float g_wV[(size_t)MAXN * D];
__device__ __align__(256) float g_z[(size_t)MAXN * HH];

// ---------------- helpers ----------------
__device__ __forceinline__ uint32_t smem_u32(const void* p) {
    uint32_t a;
    asm("{ .reg .u64 t; cvta.to.shared.u64 t, %1; cvt.u32.u64 %0, t; }" : "=r"(a) : "l"(p));
    return a;
}
__device__ __forceinline__ void ldsm4(uint32_t addr, uint32_t* r) {
    asm volatile("ldmatrix.sync.aligned.m8n8.x4.shared.b16 {%0,%1,%2,%3}, [%4];"
                 : "=r"(r[0]), "=r"(r[1]), "=r"(r[2]), "=r"(r[3]) : "r"(addr));
}
__device__ __forceinline__ void mma16816(float* c, const uint32_t* a, const uint32_t* b) {
    asm volatile("mma.sync.aligned.m16n8k16.row.col.f32.bf16.bf16.f32 "
                 "{%0,%1,%2,%3}, {%4,%5,%6,%7}, {%8,%9}, {%0,%1,%2,%3};"
                 : "+f"(c[0]), "+f"(c[1]), "+f"(c[2]), "+f"(c[3])
                 : "r"(a[0]), "r"(a[1]), "r"(a[2]), "r"(a[3]), "r"(b[0]), "r"(b[1]));
}

// ---------------- zero scratch accumulators ----------------
__global__ void zero_all() {
    size_t i = (size_t)blockIdx.x * blockDim.x + threadIdx.x;
    size_t stride = (size_t)gridDim.x * blockDim.x;
    float4 z = make_float4(0.f, 0.f, 0.f, 0.f);
    size_t nS = (size_t)NPAD * KDIM / 4;
    for (size_t j = i; j < nS; j += stride) ((float4*)g_S)[j] = z;
    size_t nW = (size_t)MAXN * D / 4;
    for (size_t j = i; j < nW; j += stride) ((float4*)g_wV)[j] = z;
    size_t nZ = (size_t)MAXN * HH / 4;
    for (size_t j = i; j < nZ; j += stride) ((float4*)g_z)[j] = z;
}

// ---------------- build W^T (bf16 hi/lo) + bias ----------------
__global__ void build_Wt(const float* __restrict__ qb, const float* __restrict__ qc, const float* __restrict__ bq,
                         const float* __restrict__ kb, const float* __restrict__ kc, const float* __restrict__ bk,
                         const float* __restrict__ vb, const float* __restrict__ vc, const float* __restrict__ bv) {
    int idx = blockIdx.x * blockDim.x + threadIdx.x;
    if (idx < NOUT)
        g_bias[idx] = (idx < D) ? bq[idx] : (idx < 2 * D) ? bk[idx - D] : bv[idx - 2 * D];
    if (idx >= NOUT * KDIM) return;
    int o = idx / KDIM;
    int k = idx - o * KDIM;
    int r = k >> 7, i2 = k & 127;
    const float* basis; const float* coef; int oo = o;
    if (o < D)          { basis = qb; coef = qc; }
    else if (o < 2 * D) { basis = kb; coef = kc; oo = o - D; }
    else                { basis = vb; coef = vc; oo = o - 2 * D; }
    float acc = 0.f;
#pragma unroll
    for (int b = 0; b < BB; b++)
        acc += coef[r * BB + b] * basis[(size_t)b * D * D + (size_t)i2 * D + oo];
    __nv_bfloat16 hi = __float2bfloat16(acc);
    __nv_bfloat16 lo = __float2bfloat16(acc - __bfloat162float(hi));
    g_Wthi[idx] = hi;
    g_Wtlo[idx] = lo;
}

// ---------------- scatter: S[dst, etype, :] += h[src, :] ----------------
__global__ void scatter_S(const float* __restrict__ h, const int* __restrict__ src,
                          const int* __restrict__ dst, const int* __restrict__ et, int E) {
    int warp = (blockIdx.x * blockDim.x + threadIdx.x) >> 5;
    if (warp >= E) return;
    int lane = threadIdx.x & 31;
    int s = __ldg(src + warp);
    int d0 = __ldg(dst + warp);
    int r = __ldg(et + warp);
    float4 v = __ldg((const float4*)(h + (size_t)s * D) + lane);
    float* p = g_S + ((size_t)d0 * KDIM + r * D + lane * 4);
    asm volatile("red.global.add.v4.f32 [%0], {%1,%2,%3,%4};"
                 :: "l"(p), "f"(v.x), "f"(v.y), "f"(v.z), "f"(v.w) : "memory");
}

// ---------------- split S into bf16 hi/lo ----------------
__global__ void split_S() {
    size_t i = (size_t)blockIdx.x * blockDim.x + threadIdx.x;
    size_t tot = (size_t)NPAD * KDIM / 4;
    if (i >= tot) return;
    float4 v = ((const float4*)g_S)[i];
    __nv_bfloat16 h0 = __float2bfloat16(v.x), h1 = __float2bfloat16(v.y);
    __nv_bfloat16 h2 = __float2bfloat16(v.z), h3 = __float2bfloat16(v.w);
    __nv_bfloat16 l0 = __float2bfloat16(v.x - __bfloat162float(h0));
    __nv_bfloat16 l1 = __float2bfloat16(v.y - __bfloat162float(h1));
    __nv_bfloat16 l2 = __float2bfloat16(v.z - __bfloat162float(h2));
    __nv_bfloat16 l3 = __float2bfloat16(v.w - __bfloat162float(h3));
    ushort4 hv, lv;
    hv.x = *(unsigned short*)&h0; hv.y = *(unsigned short*)&h1;
    hv.z = *(unsigned short*)&h2; hv.w = *(unsigned short*)&h3;
    lv.x = *(unsigned short*)&l0; lv.y = *(unsigned short*)&l1;
    lv.z = *(unsigned short*)&l2; lv.w = *(unsigned short*)&l3;
    ((ushort4*)g_Shi)[i] = hv;
    ((ushort4*)g_Slo)[i] = lv;
}

// ---------------- mma.sync bf16 split GEMM ----------------
// CTA 128x128, 8 warps (warp 32x64), K-chunk 64 bf16 (SW128 rows), 3-stage cp.async.
#define KCH        64
#define NCHUNK     (KDIM / KCH)          /* 12 */
#define TILEB      16384                  /* 128 rows x 128B */
#define STAGEB     (4 * TILEB)            /* Ahi Alo Bhi Blo */
#define NSTAGE     3
#define SMEM_TOTAL (NSTAGE * STAGEB)      /* 196608 */

__device__ __forceinline__ void load_tile256(uint32_t sdst, const __nv_bfloat16* __restrict__ g,
                                             int k0, int t) {
#pragma unroll
    for (int i = 0; i < 4; i++) {
        int u = i * 256 + t;
        int row = u >> 3, c = u & 7;
        uint32_t off = (uint32_t)(row * 128 + ((c ^ (row & 7)) * 16));
        const void* src = g + (size_t)row * KDIM + k0 + c * 8;
        asm volatile("cp.async.cg.shared.global [%0], [%1], 16;"
                     :: "r"(sdst + off), "l"(src) : "memory");
    }
}

__global__ void __launch_bounds__(256, 1) gemm_qkv_mma() {
    extern __shared__ char smem[];
    uint32_t sbase = smem_u32(smem);
    int t = threadIdx.x;
    int l = t & 31;
    int w = t >> 5;
    int wm = w & 3;           // M warp 0..3 (32 rows each)
    int wn = w >> 2;          // N warp 0..1 (64 cols each)
    int bm = blockIdx.y * 128;
    int bn = blockIdx.x * 128;

    const __nv_bfloat16* Ahi = g_Shi + (size_t)bm * KDIM;
    const __nv_bfloat16* Alo = g_Slo + (size_t)bm * KDIM;
    const __nv_bfloat16* Bhi = g_Wthi + (size_t)bn * KDIM;
    const __nv_bfloat16* Blo = g_Wtlo + (size_t)bn * KDIM;

    float acc[2][8][4];
#pragma unroll
    for (int i = 0; i < 2; i++)
#pragma unroll
        for (int j = 0; j < 8; j++)
#pragma unroll
            for (int k = 0; k < 4; k++) acc[i][j][k] = 0.f;

    // prologue: stages 0..2
#pragma unroll
    for (int c = 0; c < NSTAGE; c++) {
        uint32_t sb = sbase + c * STAGEB;
        load_tile256(sb,             Ahi, c * KCH, t);
        load_tile256(sb + TILEB,     Alo, c * KCH, t);
        load_tile256(sb + 2 * TILEB, Bhi, c * KCH, t);
        load_tile256(sb + 3 * TILEB, Blo, c * KCH, t);
        asm volatile("cp.async.commit_group;" ::: "memory");
    }

#pragma unroll 1
    for (int c = 0; c < NCHUNK; c++) {
        if (c < NCHUNK - 2)      asm volatile("cp.async.wait_group 2;" ::: "memory");
        else if (c == NCHUNK - 2) asm volatile("cp.async.wait_group 1;" ::: "memory");
        else                      asm volatile("cp.async.wait_group 0;" ::: "memory");
        __syncthreads();

        uint32_t sb = sbase + (c % NSTAGE) * STAGEB;
        uint32_t stA = sb;
        uint32_t stB = sb + 2 * TILEB;

#pragma unroll
        for (int kk = 0; kk < 4; kk++) {
            uint32_t ahi[2][4], alo[2][4], bhi[8][2], blo[8][2];
#pragma unroll
            for (int mt = 0; mt < 2; mt++) {
                uint32_t off = (uint32_t)((wm * 32 + mt * 16 + (l & 15)) * 128 +
                                          (((kk * 2 + (l >> 4)) ^ (l & 7)) * 16));
                ldsm4(stA + off, ahi[mt]);
                ldsm4(stA + TILEB + off, alo[mt]);
            }
#pragma unroll
            for (int np = 0; np < 4; np++) {
                uint32_t off = (uint32_t)((wn * 64 + np * 16 + (l & 7) + ((l >> 4) & 1) * 8) * 128 +
                                          (((kk * 2 + ((l >> 3) & 1)) ^ (l & 7)) * 16));
                uint32_t r[4];
                ldsm4(stB + off, r);
                bhi[np * 2][0] = r[0]; bhi[np * 2][1] = r[1];
                bhi[np * 2 + 1][0] = r[2]; bhi[np * 2 + 1][1] = r[3];
                ldsm4(stB + TILEB + off, r);
                blo[np * 2][0] = r[0]; blo[np * 2][1] = r[1];
                blo[np * 2 + 1][0] = r[2]; blo[np * 2 + 1][1] = r[3];
            }
#pragma unroll
            for (int mt = 0; mt < 2; mt++)
#pragma unroll
                for (int nt = 0; nt < 8; nt++) {
                    mma16816(acc[mt][nt], ahi[mt], bhi[nt]);
                    mma16816(acc[mt][nt], ahi[mt], blo[nt]);
                    mma16816(acc[mt][nt], alo[mt], bhi[nt]);
                }
        }
        __syncthreads();
        if (c + NSTAGE < NCHUNK) {
            int cn = c + NSTAGE;
            load_tile256(sb,             Ahi, cn * KCH, t);
            load_tile256(sb + TILEB,     Alo, cn * KCH, t);
            load_tile256(sb + 2 * TILEB, Bhi, cn * KCH, t);
            load_tile256(sb + 3 * TILEB, Blo, cn * KCH, t);
            asm volatile("cp.async.commit_group;" ::: "memory");
        }
    }

    // epilogue: bias + relu; rows are padded to NPAD so no bounds checks
#pragma unroll
    for (int mt = 0; mt < 2; mt++) {
        int r0 = bm + wm * 32 + mt * 16 + (l >> 2);
#pragma unroll
        for (int nt = 0; nt < 8; nt++) {
            int col = bn + wn * 64 + nt * 8 + 2 * (l & 3);
            float2 bb = *(const float2*)(g_bias + col);
            float2 o0, o1;
            o0.x = fmaxf(acc[mt][nt][0] + bb.x, 0.f);
            o0.y = fmaxf(acc[mt][nt][1] + bb.y, 0.f);
            o1.x = fmaxf(acc[mt][nt][2] + bb.x, 0.f);
            o1.y = fmaxf(acc[mt][nt][3] + bb.y, 0.f);
            *(float2*)(g_QKV + (size_t)r0 * NOUT + col) = o0;
            *(float2*)(g_QKV + (size_t)(r0 + 8) * NOUT + col) = o1;
        }
    }
}

// ---------------- attention: warp per edge ----------------
__global__ void attn_kernel(const int* __restrict__ src, const int* __restrict__ dst, int E) {
    int warp = (blockIdx.x * blockDim.x + threadIdx.x) >> 5;
    if (warp >= E) return;
    int lane = threadIdx.x & 31;
    int s = __ldg(src + warp);
    int d0 = __ldg(dst + warp);
    const float4* q4 = (const float4*)(g_QKV + (size_t)d0 * NOUT);
    const float4* k4 = (const float4*)(g_QKV + (size_t)s * NOUT + D);
    const float4* v4 = (const float4*)(g_QKV + (size_t)s * NOUT + 2 * D);
    float4 q = q4[lane], k = k4[lane], v = v4[lane];
    float p = q.x * k.x + q.y * k.y + q.z * k.z + q.w * k.w;
    p += __shfl_xor_sync(0xffffffffu, p, 1);
    p += __shfl_xor_sync(0xffffffffu, p, 2);
    float sc = fminf(fmaxf(p * 0.25f, -10.0f), 10.0f);
    float w = expf(sc);
    float* pw = g_wV + ((size_t)d0 * D + lane * 4);
    asm volatile("red.global.add.v4.f32 [%0], {%1,%2,%3,%4};"
                 :: "l"(pw), "f"(v.x * w), "f"(v.y * w), "f"(v.z * w), "f"(v.w * w) : "memory");
    if ((lane & 3) == 0)
        atomicAdd(g_z + (size_t)d0 * HH + (lane >> 2), w);
}

// ---------------- finalize ----------------
__global__ void finalize(float* __restrict__ out, int N) {
    int idx = blockIdx.x * blockDim.x + threadIdx.x;
    if (idx >= N * D) return;
    int n = idx >> 7;
    int c = idx & 127;
    out[idx] = g_wV[idx] / (g_z[n * HH + (c >> 4)] + 1e-6f);
}

extern "C" void kernel_launch(void* const* d_in, const int* in_sizes, int n_in,
                              void* d_out, int out_size) {
    const float* h   = (const float*)d_in[0];
    const int*   src = (const int*)d_in[1];
    const int*   dst = (const int*)d_in[2];
    const int*   et  = (const int*)d_in[3];
    const float* Wq_basis = (const float*)d_in[4];
    const float* Wq_coef  = (const float*)d_in[5];
    const float* bq       = (const float*)d_in[6];
    const float* Wk_basis = (const float*)d_in[7];
    const float* Wk_coef  = (const float*)d_in[8];
    const float* bk       = (const float*)d_in[9];
    const float* Wv_basis = (const float*)d_in[10];
    const float* Wv_coef  = (const float*)d_in[11];
    const float* bv       = (const float*)d_in[12];
    float* out = (float*)d_out;

    int N = in_sizes[0] / D;   // 50000
    int E = in_sizes[1];       // 500000

    static bool attr_set = false;
    if (!attr_set) {
        cudaFuncSetAttribute(gemm_qkv_mma, cudaFuncAttributeMaxDynamicSharedMemorySize, SMEM_TOTAL);
        attr_set = true;
    }

    zero_all<<<2048, 256>>>();
    build_Wt<<<(NOUT * KDIM + 255) / 256, 256>>>(Wq_basis, Wq_coef, bq,
                                                 Wk_basis, Wk_coef, bk,
                                                 Wv_basis, Wv_coef, bv);
    {
        long long threads = (long long)E * 32;
        int blocks = (int)((threads + 255) / 256);
        scatter_S<<<blocks, 256>>>(h, src, dst, et, E);
    }
    {
        long long tot = (long long)NPAD * KDIM / 4;
        split_S<<<(int)((tot + 255) / 256), 256>>>();
    }
    {
        dim3 gg(NOUT / 128, NPAD / 128);
        gemm_qkv_mma<<<gg, 256, SMEM_TOTAL>>>();
    }
    {
        long long threads = (long long)E * 32;
        int blocks = (int)((threads + 255) / 256);
        attn_kernel<<<blocks, 256>>>(src, dst, E);
    }
    finalize<<<(N * D + 255) / 256, 256>>>(out, N);
}

// round 4
// speedup vs baseline: 2.1329x; 1.2105x over previous
#include <cuda_runtime.h>
#include <cuda_bf16.h>
#include <cstdint>

#define D      128
#define HH     8
#define RR     6
#define BB     6
#define MAXN   50000
#define NPAD   50048              /* 391 * 128 */
#define KDIM   (RR * D)           /* 768 */
#define NOUT   (3 * D)            /* 384 */

// ---------------- scratch (static device globals; no allocation) ----------------
__device__ __align__(256) float g_S[(size_t)NPAD * KDIM];   // fp32 per-(dst,rel) sums
__device__ __align__(256) float g_Wt[(size_t)NOUT * KDIM];  // [384][768] K-major W^T, tf32-rounded
__device__ __align__(256) float g_bias[NOUT];
__device__ __align__(256) float g_QKV[(size_t)NPAD * NOUT]; // relu(S@W + b)
__device__ __align__(256) float g_wV[(size_t)MAXN * D];
__device__ __align__(256) float g_z[(size_t)MAXN * HH];

// ---------------- helpers ----------------
__device__ __forceinline__ uint32_t smem_u32(const void* p) {
    uint32_t a;
    asm("{ .reg .u64 t; cvta.to.shared.u64 t, %1; cvt.u32.u64 %0, t; }" : "=r"(a) : "l"(p));
    return a;
}
__device__ __forceinline__ void ldsm4(uint32_t addr, uint32_t* r) {
    asm volatile("ldmatrix.sync.aligned.m8n8.x4.shared.b16 {%0,%1,%2,%3}, [%4];"
                 : "=r"(r[0]), "=r"(r[1]), "=r"(r[2]), "=r"(r[3]) : "r"(addr));
}
__device__ __forceinline__ void mma_tf32(float* c, const uint32_t* a, const uint32_t* b) {
    asm volatile("mma.sync.aligned.m16n8k8.row.col.f32.tf32.tf32.f32 "
                 "{%0,%1,%2,%3}, {%4,%5,%6,%7}, {%8,%9}, {%0,%1,%2,%3};"
                 : "+f"(c[0]), "+f"(c[1]), "+f"(c[2]), "+f"(c[3])
                 : "r"(a[0]), "r"(a[1]), "r"(a[2]), "r"(a[3]), "r"(b[0]), "r"(b[1]));
}

// ---------------- zero scratch accumulators ----------------
__global__ void zero_all() {
    size_t i = (size_t)blockIdx.x * blockDim.x + threadIdx.x;
    size_t stride = (size_t)gridDim.x * blockDim.x;
    float4 z = make_float4(0.f, 0.f, 0.f, 0.f);
    size_t nS = (size_t)NPAD * KDIM / 4;
    for (size_t j = i; j < nS; j += stride) ((float4*)g_S)[j] = z;
    size_t nW = (size_t)MAXN * D / 4;
    for (size_t j = i; j < nW; j += stride) ((float4*)g_wV)[j] = z;
    size_t nZ = (size_t)MAXN * HH / 4;
    for (size_t j = i; j < nZ; j += stride) ((float4*)g_z)[j] = z;
}

// ---------------- build W^T (tf32-rounded fp32) + bias ----------------
__global__ void build_Wt(const float* __restrict__ qb, const float* __restrict__ qc, const float* __restrict__ bq,
                         const float* __restrict__ kb, const float* __restrict__ kc, const float* __restrict__ bk,
                         const float* __restrict__ vb, const float* __restrict__ vc, const float* __restrict__ bv) {
    int idx = blockIdx.x * blockDim.x + threadIdx.x;
    if (idx < NOUT)
        g_bias[idx] = (idx < D) ? bq[idx] : (idx < 2 * D) ? bk[idx - D] : bv[idx - 2 * D];
    if (idx >= NOUT * KDIM) return;
    int o = idx / KDIM;
    int k = idx - o * KDIM;
    int r = k >> 7, i2 = k & 127;
    const float* basis; const float* coef; int oo = o;
    if (o < D)          { basis = qb; coef = qc; }
    else if (o < 2 * D) { basis = kb; coef = kc; oo = o - D; }
    else                { basis = vb; coef = vc; oo = o - 2 * D; }
    float acc = 0.f;
#pragma unroll
    for (int b = 0; b < BB; b++)
        acc += coef[r * BB + b] * basis[(size_t)b * D * D + (size_t)i2 * D + oo];
    uint32_t bits;
    asm("cvt.rna.tf32.f32 %0, %1;" : "=r"(bits) : "f"(acc));
    g_Wt[idx] = __uint_as_float(bits);
}

// ---------------- scatter: S[dst, etype, :] += h[src, :] ----------------
__global__ void scatter_S(const float* __restrict__ h, const int* __restrict__ src,
                          const int* __restrict__ dst, const int* __restrict__ et, int E) {
    int warp = (blockIdx.x * blockDim.x + threadIdx.x) >> 5;
    if (warp >= E) return;
    int lane = threadIdx.x & 31;
    int s = __ldg(src + warp);
    int d0 = __ldg(dst + warp);
    int r = __ldg(et + warp);
    float4 v = __ldg((const float4*)(h + (size_t)s * D) + lane);
    float* p = g_S + ((size_t)d0 * KDIM + r * D + lane * 4);
    asm volatile("red.global.add.v4.f32 [%0], {%1,%2,%3,%4};"
                 :: "l"(p), "f"(v.x), "f"(v.y), "f"(v.z), "f"(v.w) : "memory");
}

// ---------------- tf32 mma.sync GEMM: QKV = relu(S @ W + b) ----------------
// CTA 128x128, 8 warps (warp 32x64), K-chunk 64 fp32 (256B rows, 16-chunk XOR swizzle),
// 3-stage cp.async pipeline. A is raw fp32 (tf32 truncation in HW), B pre-rounded rna.
#define KCH        64
#define NCHUNK     (KDIM / KCH)           /* 12 */
#define TILEB      32768                   /* 128 rows x 256B */
#define STAGEB     (2 * TILEB)             /* A + B */
#define NSTAGE     3
#define SMEM_TOTAL (NSTAGE * STAGEB)       /* 196608 */

__device__ __forceinline__ void load_tile_f32(uint32_t sdst, const float* __restrict__ g,
                                              int k0, int t) {
    // 128 rows x 256B, 16B granules: 2048 units, 8 per thread
#pragma unroll
    for (int i = 0; i < 8; i++) {
        int u = i * 256 + t;
        int row = u >> 4, c = u & 15;
        uint32_t off = (uint32_t)(row * 256 + ((c ^ (row & 15)) * 16));
        const void* src = g + (size_t)row * KDIM + k0 + c * 4;
        asm volatile("cp.async.cg.shared.global [%0], [%1], 16;"
                     :: "r"(sdst + off), "l"(src) : "memory");
    }
}

__global__ void __launch_bounds__(256, 1) gemm_qkv_tf32() {
    extern __shared__ char smem[];
    uint32_t sbase = smem_u32(smem);
    int t = threadIdx.x;
    int l = t & 31;
    int w = t >> 5;
    int wm = w & 3;           // M warp 0..3 (32 rows)
    int wn = w >> 2;          // N warp 0..1 (64 cols)
    int bm = blockIdx.y * 128;
    int bn = blockIdx.x * 128;

    const float* A = g_S + (size_t)bm * KDIM;
    const float* B = g_Wt + (size_t)bn * KDIM;

    // ldmatrix lane decomposition (constant per thread)
    int qlow = ((l >> 3) & 1) * 8 + (l & 7);  // row offset within 16-row tile
    int qhi  = l >> 4;                        // chunk offset (0/1)

    float acc[2][8][4];
#pragma unroll
    for (int i = 0; i < 2; i++)
#pragma unroll
        for (int j = 0; j < 8; j++)
#pragma unroll
            for (int k = 0; k < 4; k++) acc[i][j][k] = 0.f;

#pragma unroll
    for (int c = 0; c < NSTAGE; c++) {
        uint32_t sb = sbase + c * STAGEB;
        load_tile_f32(sb,         A, c * KCH, t);
        load_tile_f32(sb + TILEB, B, c * KCH, t);
        asm volatile("cp.async.commit_group;" ::: "memory");
    }

#pragma unroll 1
    for (int c = 0; c < NCHUNK; c++) {
        if (c < NCHUNK - 2)       asm volatile("cp.async.wait_group 2;" ::: "memory");
        else if (c == NCHUNK - 2) asm volatile("cp.async.wait_group 1;" ::: "memory");
        else                      asm volatile("cp.async.wait_group 0;" ::: "memory");
        __syncthreads();

        uint32_t sb = sbase + (c % NSTAGE) * STAGEB;
        uint32_t stA = sb;
        uint32_t stB = sb + TILEB;

#pragma unroll
        for (int ks = 0; ks < 8; ks++) {
            uint32_t af[2][4], bf[8][2];
            int sw = ((ks * 2 + qhi) ^ qlow) * 16;
#pragma unroll
            for (int mt = 0; mt < 2; mt++) {
                int row = wm * 32 + mt * 16 + qlow;
                ldsm4(stA + row * 256 + sw, af[mt]);
            }
#pragma unroll
            for (int np = 0; np < 4; np++) {
                int row = wn * 64 + np * 16 + qlow;
                uint32_t r[4];
                ldsm4(stB + row * 256 + sw, r);
                bf[np * 2][0] = r[0];     bf[np * 2][1] = r[2];
                bf[np * 2 + 1][0] = r[1]; bf[np * 2 + 1][1] = r[3];
            }
#pragma unroll
            for (int mt = 0; mt < 2; mt++)
#pragma unroll
                for (int nt = 0; nt < 8; nt++)
                    mma_tf32(acc[mt][nt], af[mt], bf[nt]);
        }
        __syncthreads();
        if (c + NSTAGE < NCHUNK) {
            int cn = c + NSTAGE;
            load_tile_f32(sb,         A, cn * KCH, t);
            load_tile_f32(sb + TILEB, B, cn * KCH, t);
            asm volatile("cp.async.commit_group;" ::: "memory");
        }
    }

    // epilogue: bias + relu (rows padded to NPAD, no bounds checks)
#pragma unroll
    for (int mt = 0; mt < 2; mt++) {
        int r0 = bm + wm * 32 + mt * 16 + (l >> 2);
#pragma unroll
        for (int nt = 0; nt < 8; nt++) {
            int col = bn + wn * 64 + nt * 8 + 2 * (l & 3);
            float2 bb = *(const float2*)(g_bias + col);
            float2 o0, o1;
            o0.x = fmaxf(acc[mt][nt][0] + bb.x, 0.f);
            o0.y = fmaxf(acc[mt][nt][1] + bb.y, 0.f);
            o1.x = fmaxf(acc[mt][nt][2] + bb.x, 0.f);
            o1.y = fmaxf(acc[mt][nt][3] + bb.y, 0.f);
            *(float2*)(g_QKV + (size_t)r0 * NOUT + col) = o0;
            *(float2*)(g_QKV + (size_t)(r0 + 8) * NOUT + col) = o1;
        }
    }
}

// ---------------- attention: warp per edge ----------------
__global__ void attn_kernel(const int* __restrict__ src, const int* __restrict__ dst, int E) {
    int warp = (blockIdx.x * blockDim.x + threadIdx.x) >> 5;
    if (warp >= E) return;
    int lane = threadIdx.x & 31;
    int s = __ldg(src + warp);
    int d0 = __ldg(dst + warp);
    const float4* q4 = (const float4*)(g_QKV + (size_t)d0 * NOUT);
    const float4* k4 = (const float4*)(g_QKV + (size_t)s * NOUT + D);
    const float4* v4 = (const float4*)(g_QKV + (size_t)s * NOUT + 2 * D);
    float4 q = q4[lane], k = k4[lane], v = v4[lane];
    float p = q.x * k.x + q.y * k.y + q.z * k.z + q.w * k.w;
    p += __shfl_xor_sync(0xffffffffu, p, 1);
    p += __shfl_xor_sync(0xffffffffu, p, 2);
    float sc = fminf(fmaxf(p * 0.25f, -10.0f), 10.0f);
    float w = expf(sc);
    float* pw = g_wV + ((size_t)d0 * D + lane * 4);
    asm volatile("red.global.add.v4.f32 [%0], {%1,%2,%3,%4};"
                 :: "l"(pw), "f"(v.x * w), "f"(v.y * w), "f"(v.z * w), "f"(v.w * w) : "memory");
    if ((lane & 3) == 0)
        atomicAdd(g_z + (size_t)d0 * HH + (lane >> 2), w);
}

// ---------------- finalize ----------------
__global__ void finalize(float* __restrict__ out, int N) {
    int idx = blockIdx.x * blockDim.x + threadIdx.x;
    if (idx >= N * D) return;
    int n = idx >> 7;
    int c = idx & 127;
    out[idx] = g_wV[idx] / (g_z[n * HH + (c >> 4)] + 1e-6f);
}

extern "C" void kernel_launch(void* const* d_in, const int* in_sizes, int n_in,
                              void* d_out, int out_size) {
    const float* h   = (const float*)d_in[0];
    const int*   src = (const int*)d_in[1];
    const int*   dst = (const int*)d_in[2];
    const int*   et  = (const int*)d_in[3];
    const float* Wq_basis = (const float*)d_in[4];
    const float* Wq_coef  = (const float*)d_in[5];
    const float* bq       = (const float*)d_in[6];
    const float* Wk_basis = (const float*)d_in[7];
    const float* Wk_coef  = (const float*)d_in[8];
    const float* bk       = (const float*)d_in[9];
    const float* Wv_basis = (const float*)d_in[10];
    const float* Wv_coef  = (const float*)d_in[11];
    const float* bv       = (const float*)d_in[12];
    float* out = (float*)d_out;

    int N = in_sizes[0] / D;   // 50000
    int E = in_sizes[1];       // 500000

    static bool attr_set = false;
    if (!attr_set) {
        cudaFuncSetAttribute(gemm_qkv_tf32, cudaFuncAttributeMaxDynamicSharedMemorySize, SMEM_TOTAL);
        attr_set = true;
    }

    zero_all<<<2048, 256>>>();
    build_Wt<<<(NOUT * KDIM + 255) / 256, 256>>>(Wq_basis, Wq_coef, bq,
                                                 Wk_basis, Wk_coef, bk,
                                                 Wv_basis, Wv_coef, bv);
    {
        long long threads = (long long)E * 32;
        int blocks = (int)((threads + 255) / 256);
        scatter_S<<<blocks, 256>>>(h, src, dst, et, E);
    }
    {
        dim3 gg(NOUT / 128, NPAD / 128);
        gemm_qkv_tf32<<<gg, 256, SMEM_TOTAL>>>();
    }
    {
        long long threads = (long long)E * 32;
        int blocks = (int)((threads + 255) / 256);
        attn_kernel<<<blocks, 256>>>(src, dst, E);
    }
    finalize<<<(N * D + 255) / 256, 256>>>(out, N);
}